// round 14
// baseline (speedup 1.0000x reference)
#include <cuda_runtime.h>
#include <cuda_bf16.h>

#define N_NODES 50000
#define N_EDGES 800000
#define HDIM    128
#define DEPTH   4
#define G_GRAPHS 512
#define BN_EPS  1e-5f
#define SCAN_BLOCKS 196   // ceil(50000/256)

// ---------------- scratch (static device memory; no allocs) ----------------
__device__ float4 g_h4  [N_NODES * 32];   // embedding output [N,128]
__device__ float4 g_hw4 [N_NODES * 32];   // h @ W            [N,128]
__device__ float4 g_agg4[N_NODES * 32];   // aggregated       [N,128]
__device__ float  g_dinv[N_NODES];
__device__ int    g_rowcnt[N_NODES];      // in-degree histogram
__device__ int    g_rowptr[N_NODES + 1];  // CSR row pointers (by dst)
__device__ int    g_cursor[N_NODES];      // fill cursors
__device__ int2   g_csr[N_EDGES];         // packed {src, bitcast(norm)}
__device__ float  g_part[250 * 2 * HDIM]; // BN partial sums
__device__ float  g_bn[2 * HDIM];         // BN scale / shift
__device__ int    g_blocksum[SCAN_BLOCKS];
__device__ int    g_blockoff[SCAN_BLOCKS];
__device__ int    g_gstart[G_GRAPHS + 1]; // per-graph row ranges (batch sorted)
__device__ unsigned long long g_w2[5 * HDIM * HDIM]; // packed tf32 {hi,lo} weights

// ---------------- tf32 helpers ---------------------------------------------
__device__ __forceinline__ unsigned f2tf32(float x) {
    unsigned r;
    asm("cvt.rna.tf32.f32 %0, %1;" : "=r"(r) : "f"(x));
    return r;
}
// D += A(m16k8,row) * B(k8n8,col), tf32 inputs, f32 accum
__device__ __forceinline__ void mma_tf32(float* c, const unsigned* a,
                                         unsigned b0, unsigned b1) {
    asm("mma.sync.aligned.m16n8k8.row.col.f32.tf32.tf32.f32 "
        "{%0,%1,%2,%3},{%4,%5,%6,%7},{%8,%9},{%0,%1,%2,%3};"
        : "+f"(c[0]), "+f"(c[1]), "+f"(c[2]), "+f"(c[3])
        : "r"(a[0]), "r"(a[1]), "r"(a[2]), "r"(a[3]), "r"(b0), "r"(b1));
}

// ---------------- init ----------------
__global__ void k_zero_cnt() {
    int i = blockIdx.x * 256 + threadIdx.x;
    if (i < N_NODES) g_rowcnt[i] = 0;
}

// ---------------- W split: pack {tf32 hi, tf32 lo} per element -------------
__global__ void k_wsplit(const float* __restrict__ W_emb,
                         const float* __restrict__ W_conv) {
    int i = blockIdx.x * 256 + threadIdx.x;
    if (i >= 5 * HDIM * HDIM) return;
    float w = (i < HDIM * HDIM) ? W_emb[i] : W_conv[i - HDIM * HDIM];
    unsigned hi = f2tf32(w);
    float lof = w - __uint_as_float(hi);
    unsigned lo = f2tf32(lof);
    g_w2[i] = ((unsigned long long)lo << 32) | hi;
}

// ---------------- degree histogram ----------------
__global__ void k_deg(const int* __restrict__ ei) {
    int e = blockIdx.x * 256 + threadIdx.x;
    if (e < N_EDGES) atomicAdd(&g_rowcnt[ei[N_EDGES + e]], 1);
}

// ---------------- multi-block exclusive scan of rowcnt -> rowptr -----------
__global__ __launch_bounds__(256) void k_scan1() {
    __shared__ int wsum[8];
    int t = threadIdx.x, lane = t & 31, w = t >> 5;
    int i = blockIdx.x * 256 + t;
    int v = (i < N_NODES) ? g_rowcnt[i] : 0;
    int s = v;
#pragma unroll
    for (int off = 1; off < 32; off <<= 1) {
        int tmp = __shfl_up_sync(0xffffffffu, s, off);
        if (lane >= off) s += tmp;
    }
    if (lane == 31) wsum[w] = s;
    __syncthreads();
    if (t == 0) {
        int tot = 0;
#pragma unroll
        for (int j = 0; j < 8; j++) tot += wsum[j];
        g_blocksum[blockIdx.x] = tot;
    }
}

__global__ __launch_bounds__(256) void k_scan2() {
    __shared__ int wsum[8];
    int t = threadIdx.x, lane = t & 31, w = t >> 5;
    int v = (t < SCAN_BLOCKS) ? g_blocksum[t] : 0;
    int s = v;
#pragma unroll
    for (int off = 1; off < 32; off <<= 1) {
        int tmp = __shfl_up_sync(0xffffffffu, s, off);
        if (lane >= off) s += tmp;
    }
    if (lane == 31) wsum[w] = s;
    __syncthreads();
    if (t == 0) {
        int run = 0;
#pragma unroll
        for (int j = 0; j < 8; j++) { int x = wsum[j]; wsum[j] = run; run += x; }
    }
    __syncthreads();
    if (t < SCAN_BLOCKS) g_blockoff[t] = wsum[w] + s - v;   // exclusive
}

// scan3: finishes rowptr/cursor AND computes dinv
__global__ __launch_bounds__(256) void k_scan3() {
    __shared__ int wsum[8];
    int t = threadIdx.x, lane = t & 31, w = t >> 5;
    int i = blockIdx.x * 256 + t;
    int v = (i < N_NODES) ? g_rowcnt[i] : 0;
    int s = v;
#pragma unroll
    for (int off = 1; off < 32; off <<= 1) {
        int tmp = __shfl_up_sync(0xffffffffu, s, off);
        if (lane >= off) s += tmp;
    }
    if (lane == 31) wsum[w] = s;
    __syncthreads();
    if (t == 0) {
        int run = 0;
#pragma unroll
        for (int j = 0; j < 8; j++) { int x = wsum[j]; wsum[j] = run; run += x; }
    }
    __syncthreads();
    if (i < N_NODES) {
        int excl = g_blockoff[blockIdx.x] + wsum[w] + s - v;
        g_rowptr[i] = excl;
        g_cursor[i] = excl;
        g_dinv[i]   = rsqrtf((float)v + 1.0f);
    }
    if (blockIdx.x == 0 && t == 0) g_rowptr[N_NODES] = N_EDGES;
}

// ---------------- CSR fill: packed {src, full norm} ----------------
__global__ void k_fill(const int* __restrict__ ei) {
    int e = blockIdx.x * 256 + threadIdx.x;
    if (e >= N_EDGES) return;
    int src = ei[e];
    int dst = ei[N_EDGES + e];
    int pos = atomicAdd(&g_cursor[dst], 1);
    float norm = g_dinv[src] * g_dinv[dst];
    g_csr[pos] = make_int2(src, __float_as_int(norm));
}

// ---------------- graph boundaries (batch is sorted) ----------------
__global__ void k_gbound(const int* __restrict__ batch) {
    int i = blockIdx.x * 256 + threadIdx.x;
    if (i >= N_NODES) return;
    int b = batch[i];
    int prev = (i == 0) ? -1 : batch[i - 1];
    for (int g = prev + 1; g <= b; g++) g_gstart[g] = i;
    if (i == N_NODES - 1)
        for (int g = b + 1; g <= G_GRAPHS; g++) g_gstart[g] = N_NODES;
}

// ---------------- Tensor-core GEMM (tf32 2-split): C = pre(A) @ W (+bias) --
// 128-row blocks, 8 warps, each warp owns a m16 slab x all 128 cols.
// A fragments straight from global (each element read once per block),
// bn+relu fused, split to tf32 hi/lo in registers. W pre-split in g_w2.
// No shared memory, no block syncs.
__global__ __launch_bounds__(256, 2) void k_gemm_tc(
        const float* __restrict__ A,
        const unsigned long long* __restrict__ W2,
        const float* __restrict__ bias,
        const float* __restrict__ bn,
        float* __restrict__ C,
        int nrows) {
    const int warp = threadIdx.x >> 5;
    const int lane = threadIdx.x & 31;
    const int gid  = lane >> 2;     // 0..7
    const int tig  = lane & 3;      // 0..3
    const int m0   = blockIdx.x * 128 + warp * 16;
    const int r0   = m0 + gid;      // rows gid, gid+8 of the m16 slab
    const int r1   = m0 + gid + 8;
    const bool ok0 = (r0 < nrows), ok1 = (r1 < nrows);

    float acc[16][4];
#pragma unroll
    for (int nt = 0; nt < 16; nt++)
#pragma unroll
        for (int j = 0; j < 4; j++) acc[nt][j] = 0.f;

#pragma unroll 1
    for (int ks = 0; ks < 16; ks++) {
        const int ca = ks * 8 + tig;       // k columns for a0/a1
        const int cb = ca + 4;             // k columns for a2/a3
        float a[4];
        a[0] = ok0 ? __ldg(&A[r0 * 128 + ca]) : 0.f;
        a[1] = ok1 ? __ldg(&A[r1 * 128 + ca]) : 0.f;
        a[2] = ok0 ? __ldg(&A[r0 * 128 + cb]) : 0.f;
        a[3] = ok1 ? __ldg(&A[r1 * 128 + cb]) : 0.f;
        if (bn != nullptr) {
            float sa = __ldg(&bn[ca]), ha = __ldg(&bn[HDIM + ca]);
            float sb = __ldg(&bn[cb]), hb = __ldg(&bn[HDIM + cb]);
            a[0] = fmaxf(a[0], 0.f) * sa + ha;
            a[1] = fmaxf(a[1], 0.f) * sa + ha;
            a[2] = fmaxf(a[2], 0.f) * sb + hb;
            a[3] = fmaxf(a[3], 0.f) * sb + hb;
            if (!ok0) { a[0] = 0.f; a[2] = 0.f; }
            if (!ok1) { a[1] = 0.f; a[3] = 0.f; }
        }
        unsigned ahi[4], alo[4];
#pragma unroll
        for (int j = 0; j < 4; j++) {
            ahi[j] = f2tf32(a[j]);
            alo[j] = f2tf32(a[j] - __uint_as_float(ahi[j]));
        }
        const unsigned long long* w0 = W2 + ca * HDIM + gid;
        const unsigned long long* w1 = W2 + cb * HDIM + gid;
#pragma unroll
        for (int nt = 0; nt < 16; nt++) {
            uint2 b0 = *(const uint2*)&w0[nt * 8];   // {hi, lo} of W[ca][n]
            uint2 b1 = *(const uint2*)&w1[nt * 8];   // {hi, lo} of W[cb][n]
            mma_tf32(acc[nt], ahi, b0.x, b1.x);      // Ahi * Bhi
            mma_tf32(acc[nt], ahi, b0.y, b1.y);      // Ahi * Blo
            mma_tf32(acc[nt], alo, b0.x, b1.x);      // Alo * Bhi
        }
    }

    // epilogue: c0,c1 -> (r0, n..n+1); c2,c3 -> (r1, n..n+1)
#pragma unroll
    for (int nt = 0; nt < 16; nt++) {
        int n = nt * 8 + tig * 2;
        float2 v0 = make_float2(acc[nt][0], acc[nt][1]);
        float2 v1 = make_float2(acc[nt][2], acc[nt][3]);
        if (bias != nullptr) {
            float b0 = __ldg(&bias[n]), b1 = __ldg(&bias[n + 1]);
            v0.x += b0; v0.y += b1;
            v1.x += b0; v1.y += b1;
        }
        if (ok0) *(float2*)&C[r0 * 128 + n] = v0;
        if (ok1) *(float2*)&C[r1 * 128 + n] = v1;
    }
}

// ---------------- pull aggregation: one warp per dst node (independent) ----
__global__ __launch_bounds__(256) void k_agg(const float* __restrict__ bias) {
    int node = blockIdx.x * 8 + (threadIdx.x >> 5);
    if (node >= N_NODES) return;
    int lane = threadIdx.x & 31;
    int beg = g_rowptr[node], end = g_rowptr[node + 1];
    float dv = g_dinv[node];

    float4 acc = make_float4(0.f, 0.f, 0.f, 0.f);
#pragma unroll 4
    for (int j = beg; j < end; j++) {
        int2 ed  = __ldg(&g_csr[j]);             // one LDG.64, warp-broadcast
        float nw = __int_as_float(ed.y);
        float4 v = g_hw4[ed.x * 32 + lane];
        acc.x += nw * v.x; acc.y += nw * v.y;
        acc.z += nw * v.z; acc.w += nw * v.w;
    }
    float d2 = dv * dv;
    float4 s = g_hw4[node * 32 + lane];
    acc.x = acc.x + d2 * s.x + bias[lane * 4 + 0];
    acc.y = acc.y + d2 * s.y + bias[lane * 4 + 1];
    acc.z = acc.z + d2 * s.z + bias[lane * 4 + 2];
    acc.w = acc.w + d2 * s.w + bias[lane * 4 + 3];
    g_agg4[node * 32 + lane] = acc;
}

// ---------------- BN: partial sums over relu(agg) (atomic-free) ------------
__global__ __launch_bounds__(128) void k_bnreduce() {
    const int c = threadIdx.x;
    const int rows_per = 200;                 // 250 * 200 = 50000
    int r0 = blockIdx.x * rows_per;
    int r1 = r0 + rows_per; if (r1 > N_NODES) r1 = N_NODES;
    const float* agg = (const float*)g_agg4;
    float s = 0.f, q = 0.f;
    for (int r = r0; r < r1; r++) {
        float v = fmaxf(__ldg(&agg[r * HDIM + c]), 0.f);
        s += v; q += v * v;
    }
    g_part[blockIdx.x * 2 * HDIM + c] = s;
    g_part[blockIdx.x * 2 * HDIM + HDIM + c] = q;
}

__global__ __launch_bounds__(128) void k_bnfinal(const float* __restrict__ gamma,
                                                 const float* __restrict__ beta) {
    const int c = threadIdx.x;
    float s = 0.f, q = 0.f;
    for (int b = 0; b < 250; b++) {
        s += g_part[b * 2 * HDIM + c];
        q += g_part[b * 2 * HDIM + HDIM + c];
    }
    float inv_n = 1.0f / (float)N_NODES;
    float mu  = s * inv_n;
    float var = q * inv_n - mu * mu;
    float sc  = rsqrtf(var + BN_EPS) * gamma[c];
    g_bn[c]        = sc;
    g_bn[HDIM + c] = beta[c] - mu * sc;
}

// ---------------- pooling: one block per graph (batch sorted, no atomics) --
__global__ __launch_bounds__(128) void k_pool(float* __restrict__ out) {
    int g = blockIdx.x, c = threadIdx.x;
    int r0 = g_gstart[g], r1 = g_gstart[g + 1];
    const float* agg = (const float*)g_agg4;
    float s = 0.f;
    for (int r = r0; r < r1; r++) s += __ldg(&agg[r * HDIM + c]);
    out[g * HDIM + c] = s / fmaxf((float)(r1 - r0), 1.0f);
}

// ---------------- launcher -------------------------------------------------
extern "C" void kernel_launch(void* const* d_in, const int* in_sizes, int n_in,
                              void* d_out, int out_size) {
    const float* x      = (const float*)d_in[0];
    const int*   ei     = (const int*)d_in[1];     // int32 (JAX coerces int64)
    const int*   batch  = (const int*)d_in[2];     // int32
    const float* W_emb  = (const float*)d_in[3];
    const float* b_emb  = (const float*)d_in[4];
    const float* W_conv = (const float*)d_in[5];
    const float* b_conv = (const float*)d_in[6];
    const float* gamma  = (const float*)d_in[7];
    const float* beta   = (const float*)d_in[8];
    float* out = (float*)d_out;

    float *p_h, *p_hw, *p_agg, *p_bn;
    unsigned long long* p_w2;
    cudaGetSymbolAddress((void**)&p_h,   g_h4);
    cudaGetSymbolAddress((void**)&p_hw,  g_hw4);
    cudaGetSymbolAddress((void**)&p_agg, g_agg4);
    cudaGetSymbolAddress((void**)&p_bn,  g_bn);
    cudaGetSymbolAddress((void**)&p_w2,  g_w2);

    const int GEMM_BLOCKS = (N_NODES + 127) / 128;        // 391
    const int NODE_BLOCKS = (N_NODES + 255) / 256;        // 196
    const int EDGE_BLOCKS = (N_EDGES + 255) / 256;        // 3125
    const int AGG_BLOCKS  = N_NODES / 8;                  // 6250 (exact)

    // graph preprocessing + weight splitting
    k_zero_cnt<<<NODE_BLOCKS, 256>>>();
    k_wsplit<<<(5 * HDIM * HDIM + 255) / 256, 256>>>(W_emb, W_conv);
    k_deg<<<EDGE_BLOCKS, 256>>>(ei);
    k_scan1<<<SCAN_BLOCKS, 256>>>();
    k_scan2<<<1, 256>>>();
    k_scan3<<<SCAN_BLOCKS, 256>>>();
    k_fill<<<EDGE_BLOCKS, 256>>>(ei);
    k_gbound<<<NODE_BLOCKS, 256>>>(batch);

    // embedding: h = x @ W_emb + b_emb
    k_gemm_tc<<<GEMM_BLOCKS, 256>>>(x, p_w2, b_emb, nullptr, p_h, N_NODES);

    for (int i = 0; i < DEPTH; i++) {
        const float* Ain = (i == 0) ? p_h : p_agg;
        const float* bn  = (i == 0) ? nullptr : p_bn;   // fused relu+BN of prev layer
        k_gemm_tc<<<GEMM_BLOCKS, 256>>>(Ain, p_w2 + (1 + i) * HDIM * HDIM,
                                        nullptr, bn, p_hw, N_NODES);
        k_agg<<<AGG_BLOCKS, 256>>>(b_conv + i * HDIM);
        if (i < DEPTH - 1) {
            k_bnreduce<<<250, 128>>>();
            k_bnfinal<<<1, 128>>>(gamma + i * HDIM, beta + i * HDIM);
        }
    }

    k_pool<<<G_GRAPHS, 128>>>(out);
}

// round 15
// speedup vs baseline: 1.3245x; 1.3245x over previous
#include <cuda_runtime.h>
#include <cuda_bf16.h>

#define N_NODES 50000
#define N_EDGES 800000
#define HDIM    128
#define DEPTH   4
#define G_GRAPHS 512
#define BN_EPS  1e-5f
#define SCAN_BLOCKS 196   // ceil(50000/256)

// ---------------- scratch (static device memory; no allocs) ----------------
__device__ float4 g_h4  [N_NODES * 32];   // embedding output [N,128]
__device__ float4 g_hw4 [N_NODES * 32];   // h @ W            [N,128]
__device__ float4 g_agg4[N_NODES * 32];   // aggregated       [N,128]
__device__ float  g_dinv[N_NODES];
__device__ int    g_rowcnt[N_NODES];      // in-degree histogram
__device__ int    g_rowptr[N_NODES + 1];  // CSR row pointers (by dst)
__device__ int    g_cursor[N_NODES];      // fill cursors
__device__ int2   g_csr[N_EDGES];         // packed {src, bitcast(norm)}
__device__ float  g_part[250 * 2 * HDIM]; // BN partial sums
__device__ float  g_bn[2 * HDIM];         // BN scale / shift
__device__ int    g_blocksum[SCAN_BLOCKS];
__device__ int    g_gstart[G_GRAPHS + 1]; // per-graph row ranges (batch sorted)
__device__ int    g_bnctr[DEPTH - 1];     // last-block-done counters

// ---------------- packed f32x2 helpers (Blackwell FFMA2) -------------------
__device__ __forceinline__ void fma2(unsigned long long& d,
                                     unsigned long long a,
                                     unsigned long long b) {
    asm("fma.rn.f32x2 %0, %1, %2, %0;" : "+l"(d) : "l"(a), "l"(b));
}
__device__ __forceinline__ unsigned long long pack2(float x, float y) {
    unsigned long long r;
    asm("mov.b64 %0, {%1, %2};" : "=l"(r) : "f"(x), "f"(y));
    return r;
}
__device__ __forceinline__ float lo32(unsigned long long v) {
    return __uint_as_float((unsigned int)(v & 0xffffffffull));
}
__device__ __forceinline__ float hi32(unsigned long long v) {
    return __uint_as_float((unsigned int)(v >> 32));
}

// ---------------- init: rowcnt zero + graph bounds + BN counters -----------
__global__ void k_init(const int* __restrict__ batch) {
    int i = blockIdx.x * 256 + threadIdx.x;
    if (i < N_NODES) {
        g_rowcnt[i] = 0;
        int b = batch[i];
        int prev = (i == 0) ? -1 : batch[i - 1];
        for (int g = prev + 1; g <= b; g++) g_gstart[g] = i;
        if (i == N_NODES - 1)
            for (int g = b + 1; g <= G_GRAPHS; g++) g_gstart[g] = N_NODES;
    }
    if (i < DEPTH - 1) g_bnctr[i] = 0;
}

// ---------------- degree histogram ----------------
__global__ void k_deg(const int* __restrict__ ei) {
    int e = blockIdx.x * 256 + threadIdx.x;
    if (e < N_EDGES) atomicAdd(&g_rowcnt[ei[N_EDGES + e]], 1);
}

// ---------------- scan stage 1: per-block sums -----------------------------
__global__ __launch_bounds__(256) void k_scan1() {
    __shared__ int wsum[8];
    int t = threadIdx.x, lane = t & 31, w = t >> 5;
    int i = blockIdx.x * 256 + t;
    int v = (i < N_NODES) ? g_rowcnt[i] : 0;
    int s = v;
#pragma unroll
    for (int off = 1; off < 32; off <<= 1) {
        int tmp = __shfl_up_sync(0xffffffffu, s, off);
        if (lane >= off) s += tmp;
    }
    if (lane == 31) wsum[w] = s;
    __syncthreads();
    if (t == 0) {
        int tot = 0;
#pragma unroll
        for (int j = 0; j < 8; j++) tot += wsum[j];
        g_blocksum[blockIdx.x] = tot;
    }
}

// scan stage 2 (fused): each block scans the 196 block sums itself, then
// finishes rowptr/cursor/dinv for its 256 nodes.
__global__ __launch_bounds__(256) void k_scan3() {
    __shared__ int wsum[8];
    __shared__ int s_off[256];
    int t = threadIdx.x, lane = t & 31, w = t >> 5;

    // --- in-block exclusive scan of the 196 block sums ---
    {
        int v = (t < SCAN_BLOCKS) ? g_blocksum[t] : 0;
        int s = v;
#pragma unroll
        for (int off = 1; off < 32; off <<= 1) {
            int tmp = __shfl_up_sync(0xffffffffu, s, off);
            if (lane >= off) s += tmp;
        }
        if (lane == 31) wsum[w] = s;
        __syncthreads();
        if (t == 0) {
            int run = 0;
#pragma unroll
            for (int j = 0; j < 8; j++) { int x = wsum[j]; wsum[j] = run; run += x; }
        }
        __syncthreads();
        s_off[t] = wsum[w] + s - v;     // exclusive prefix of blocksum[t]
        __syncthreads();
    }
    const int base = s_off[blockIdx.x];
    __syncthreads();                     // protect wsum reuse below

    // --- in-block exclusive scan of this block's 256 counts ---
    int i = blockIdx.x * 256 + t;
    int v = (i < N_NODES) ? g_rowcnt[i] : 0;
    int s = v;
#pragma unroll
    for (int off = 1; off < 32; off <<= 1) {
        int tmp = __shfl_up_sync(0xffffffffu, s, off);
        if (lane >= off) s += tmp;
    }
    if (lane == 31) wsum[w] = s;
    __syncthreads();
    if (t == 0) {
        int run = 0;
#pragma unroll
        for (int j = 0; j < 8; j++) { int x = wsum[j]; wsum[j] = run; run += x; }
    }
    __syncthreads();
    if (i < N_NODES) {
        int excl = base + wsum[w] + s - v;
        g_rowptr[i] = excl;
        g_cursor[i] = excl;
        g_dinv[i]   = rsqrtf((float)v + 1.0f);
    }
    if (blockIdx.x == 0 && t == 0) g_rowptr[N_NODES] = N_EDGES;
}

// ---------------- CSR fill: packed {src, full norm} ----------------
__global__ void k_fill(const int* __restrict__ ei) {
    int e = blockIdx.x * 256 + threadIdx.x;
    if (e >= N_EDGES) return;
    int src = ei[e];
    int dst = ei[N_EDGES + e];
    int pos = atomicAdd(&g_cursor[dst], 1);
    float norm = g_dinv[src] * g_dinv[dst];
    g_csr[pos] = make_int2(src, __float_as_int(norm));
}

// ---------------- GEMM (FFMA2): C = pre(A) @ W (+bias) ---------------------
// A staged TRANSPOSED (sAT[k][m], pad 66 keeps LDS.64 8B-aligned) so M-row-
// pairs load DIRECTLY as 64-bit values (no pack movs) for fma.rn.f32x2.
// If bn != null: a <- max(a,0)*bn[k] + bn[128+k] fused on load.
__global__ __launch_bounds__(256) void k_gemm(const float* __restrict__ A,
                                              const float* __restrict__ W,
                                              const float* __restrict__ bias,
                                              const float* __restrict__ bn,
                                              float* __restrict__ C,
                                              int nrows) {
    __shared__ float sAT[32][66];
    __shared__ float sW[32][128];
    const int tid = threadIdx.x;
    const int tx  = tid & 31;    // -> cols tx*4 .. tx*4+3
    const int ty  = tid >> 5;    // -> rows ty*8 .. ty*8+7
    const int m0  = blockIdx.x * 64;

    unsigned long long acc[4][4];   // [row-pair][col]
#pragma unroll
    for (int p = 0; p < 4; p++)
#pragma unroll
        for (int c = 0; c < 4; c++) acc[p][c] = 0ull;

    for (int kc = 0; kc < 128; kc += 32) {
#pragma unroll
        for (int i = 0; i < 8; i++) {
            int idx = tid + i * 256;
            int m = idx >> 5, k = idx & 31;
            int row = m0 + m;
            float a = (row < nrows) ? A[row * 128 + kc + k] : 0.f;
            if (bn != nullptr)
                a = fmaxf(a, 0.f) * bn[kc + k] + bn[HDIM + kc + k];
            sAT[k][m] = a;
        }
#pragma unroll
        for (int i = 0; i < 16; i++) {
            int idx = tid + i * 256;
            int k = idx >> 7, n = idx & 127;
            sW[k][n] = W[(kc + k) * 128 + n];
        }
        __syncthreads();
#pragma unroll
        for (int k = 0; k < 32; k++) {
            const float* ar = &sAT[k][ty * 8];
            unsigned long long ap[4] = {
                *(const unsigned long long*)(ar + 0),
                *(const unsigned long long*)(ar + 2),
                *(const unsigned long long*)(ar + 4),
                *(const unsigned long long*)(ar + 6)
            };
            float4 w = *(const float4*)&sW[k][tx * 4];
            unsigned long long wp[4] = {
                pack2(w.x, w.x), pack2(w.y, w.y),
                pack2(w.z, w.z), pack2(w.w, w.w)
            };
#pragma unroll
            for (int p = 0; p < 4; p++)
#pragma unroll
                for (int c = 0; c < 4; c++)
                    fma2(acc[p][c], ap[p], wp[c]);
        }
        __syncthreads();
    }
#pragma unroll
    for (int r = 0; r < 8; r++) {
        int row = m0 + ty * 8 + r;
        if (row < nrows) {
            int p = r >> 1;
            float4 v;
            if (r & 1) {
                v.x = hi32(acc[p][0]); v.y = hi32(acc[p][1]);
                v.z = hi32(acc[p][2]); v.w = hi32(acc[p][3]);
            } else {
                v.x = lo32(acc[p][0]); v.y = lo32(acc[p][1]);
                v.z = lo32(acc[p][2]); v.w = lo32(acc[p][3]);
            }
            if (bias != nullptr) {
                v.x += bias[tx * 4 + 0]; v.y += bias[tx * 4 + 1];
                v.z += bias[tx * 4 + 2]; v.w += bias[tx * 4 + 3];
            }
            *(float4*)&C[row * 128 + tx * 4] = v;
        }
    }
}

// ---------------- pull aggregation: one warp per dst node (independent) ----
__global__ __launch_bounds__(256) void k_agg(const float* __restrict__ bias) {
    int node = blockIdx.x * 8 + (threadIdx.x >> 5);
    if (node >= N_NODES) return;
    int lane = threadIdx.x & 31;
    int beg = g_rowptr[node], end = g_rowptr[node + 1];
    float dv = g_dinv[node];

    float4 acc = make_float4(0.f, 0.f, 0.f, 0.f);
#pragma unroll 4
    for (int j = beg; j < end; j++) {
        int2 ed  = __ldg(&g_csr[j]);             // one LDG.64, warp-broadcast
        float nw = __int_as_float(ed.y);
        float4 v = g_hw4[ed.x * 32 + lane];
        acc.x += nw * v.x; acc.y += nw * v.y;
        acc.z += nw * v.z; acc.w += nw * v.w;
    }
    float d2 = dv * dv;
    float4 s = g_hw4[node * 32 + lane];
    acc.x = acc.x + d2 * s.x + bias[lane * 4 + 0];
    acc.y = acc.y + d2 * s.y + bias[lane * 4 + 1];
    acc.z = acc.z + d2 * s.z + bias[lane * 4 + 2];
    acc.w = acc.w + d2 * s.w + bias[lane * 4 + 3];
    g_agg4[node * 32 + lane] = acc;
}

// ---------------- BN: partials + fused last-block finalize -----------------
// 250 blocks x 128 threads. Each block writes its partial sums, then the
// LAST block to finish reduces all partials and writes g_bn (deterministic:
// the final sum is over fixed indices in fixed order).
__global__ __launch_bounds__(128) void k_bnreduce(const float* __restrict__ gamma,
                                                  const float* __restrict__ beta,
                                                  int layer) {
    const int c = threadIdx.x;
    const int rows_per = 200;                 // 250 * 200 = 50000
    int r0 = blockIdx.x * rows_per;
    int r1 = r0 + rows_per; if (r1 > N_NODES) r1 = N_NODES;
    const float* agg = (const float*)g_agg4;
    float s = 0.f, q = 0.f;
    for (int r = r0; r < r1; r++) {
        float v = fmaxf(__ldg(&agg[r * HDIM + c]), 0.f);
        s += v; q += v * v;
    }
    g_part[blockIdx.x * 2 * HDIM + c] = s;
    g_part[blockIdx.x * 2 * HDIM + HDIM + c] = q;

    __threadfence();
    __shared__ int s_last;
    if (c == 0) s_last = (atomicAdd(&g_bnctr[layer], 1) == 249) ? 1 : 0;
    __syncthreads();
    if (s_last) {
        float ts = 0.f, tq = 0.f;
        for (int b = 0; b < 250; b++) {
            ts += g_part[b * 2 * HDIM + c];
            tq += g_part[b * 2 * HDIM + HDIM + c];
        }
        float inv_n = 1.0f / (float)N_NODES;
        float mu  = ts * inv_n;
        float var = tq * inv_n - mu * mu;
        float sc  = rsqrtf(var + BN_EPS) * gamma[c];
        g_bn[c]        = sc;
        g_bn[HDIM + c] = beta[c] - mu * sc;
    }
}

// ---------------- pooling: one block per graph (batch sorted, no atomics) --
__global__ __launch_bounds__(128) void k_pool(float* __restrict__ out) {
    int g = blockIdx.x, c = threadIdx.x;
    int r0 = g_gstart[g], r1 = g_gstart[g + 1];
    const float* agg = (const float*)g_agg4;
    float s = 0.f;
    for (int r = r0; r < r1; r++) s += __ldg(&agg[r * HDIM + c]);
    out[g * HDIM + c] = s / fmaxf((float)(r1 - r0), 1.0f);
}

// ---------------- launcher -------------------------------------------------
extern "C" void kernel_launch(void* const* d_in, const int* in_sizes, int n_in,
                              void* d_out, int out_size) {
    const float* x      = (const float*)d_in[0];
    const int*   ei     = (const int*)d_in[1];     // int32 (JAX coerces int64)
    const int*   batch  = (const int*)d_in[2];     // int32
    const float* W_emb  = (const float*)d_in[3];
    const float* b_emb  = (const float*)d_in[4];
    const float* W_conv = (const float*)d_in[5];
    const float* b_conv = (const float*)d_in[6];
    const float* gamma  = (const float*)d_in[7];
    const float* beta   = (const float*)d_in[8];
    float* out = (float*)d_out;

    float *p_h, *p_hw, *p_agg, *p_bn;
    cudaGetSymbolAddress((void**)&p_h,   g_h4);
    cudaGetSymbolAddress((void**)&p_hw,  g_hw4);
    cudaGetSymbolAddress((void**)&p_agg, g_agg4);
    cudaGetSymbolAddress((void**)&p_bn,  g_bn);

    const int GEMM_BLOCKS = (N_NODES + 63) / 64;          // 782
    const int NODE_BLOCKS = (N_NODES + 255) / 256;        // 196
    const int EDGE_BLOCKS = (N_EDGES + 255) / 256;        // 3125
    const int AGG_BLOCKS  = N_NODES / 8;                  // 6250 (exact)

    // graph preprocessing (5 launches)
    k_init<<<NODE_BLOCKS, 256>>>(batch);
    k_deg<<<EDGE_BLOCKS, 256>>>(ei);
    k_scan1<<<SCAN_BLOCKS, 256>>>();
    k_scan3<<<SCAN_BLOCKS, 256>>>();
    k_fill<<<EDGE_BLOCKS, 256>>>(ei);

    // embedding: h = x @ W_emb + b_emb
    k_gemm<<<GEMM_BLOCKS, 256>>>(x, W_emb, b_emb, nullptr, p_h, N_NODES);

    for (int i = 0; i < DEPTH; i++) {
        const float* Ain = (i == 0) ? p_h : p_agg;
        const float* bn  = (i == 0) ? nullptr : p_bn;   // fused relu+BN of prev layer
        k_gemm<<<GEMM_BLOCKS, 256>>>(Ain, W_conv + i * HDIM * HDIM, nullptr,
                                     bn, p_hw, N_NODES);
        k_agg<<<AGG_BLOCKS, 256>>>(b_conv + i * HDIM);
        if (i < DEPTH - 1)
            k_bnreduce<<<250, 128>>>(gamma + i * HDIM, beta + i * HDIM, i);
    }

    k_pool<<<G_GRAPHS, 128>>>(out);
}

// round 17
// speedup vs baseline: 1.3664x; 1.0316x over previous
#include <cuda_runtime.h>
#include <cuda_bf16.h>

#define N_NODES 50000
#define N_EDGES 800000
#define HDIM    128
#define DEPTH   4
#define G_GRAPHS 512
#define BN_EPS  1e-5f
#define SCAN_BLOCKS 196   // ceil(50000/256)

// ---------------- scratch (static device memory; no allocs) ----------------
__device__ float4 g_h4  [N_NODES * 32];   // embedding output [N,128]
__device__ float4 g_hw4 [N_NODES * 32];   // h @ W            [N,128]
__device__ float4 g_agg4[N_NODES * 32];   // aggregated       [N,128]
__device__ float  g_dinv[N_NODES];
__device__ int    g_rowcnt[N_NODES];      // in-degree histogram
__device__ int    g_rowptr[N_NODES + 1];  // CSR row pointers (by dst)
__device__ int    g_cursor[N_NODES];      // fill cursors
__device__ int2   g_csr[N_EDGES];         // packed {src, bitcast(norm)}
__device__ float  g_part[250 * 2 * HDIM]; // BN partial sums
__device__ float  g_bn[2 * HDIM];         // BN scale / shift
__device__ int    g_blocksum[SCAN_BLOCKS];
__device__ int    g_gstart[G_GRAPHS + 1]; // per-graph row ranges (batch sorted)
__device__ int    g_bnctr[DEPTH - 1];     // last-block-done counters

// ---------------- packed f32x2 helpers (Blackwell FFMA2) -------------------
__device__ __forceinline__ void fma2(unsigned long long& d,
                                     unsigned long long a,
                                     unsigned long long b) {
    asm("fma.rn.f32x2 %0, %1, %2, %0;" : "+l"(d) : "l"(a), "l"(b));
}
__device__ __forceinline__ unsigned long long pack2(float x, float y) {
    unsigned long long r;
    asm("mov.b64 %0, {%1, %2};" : "=l"(r) : "f"(x), "f"(y));
    return r;
}
__device__ __forceinline__ float lo32(unsigned long long v) {
    return __uint_as_float((unsigned int)(v & 0xffffffffull));
}
__device__ __forceinline__ float hi32(unsigned long long v) {
    return __uint_as_float((unsigned int)(v >> 32));
}

// ---------------- init: rowcnt zero + graph bounds + BN counters -----------
__global__ void k_init(const int* __restrict__ batch) {
    int i = blockIdx.x * 256 + threadIdx.x;
    if (i < N_NODES) {
        g_rowcnt[i] = 0;
        int b = batch[i];
        int prev = (i == 0) ? -1 : batch[i - 1];
        for (int g = prev + 1; g <= b; g++) g_gstart[g] = i;
        if (i == N_NODES - 1)
            for (int g = b + 1; g <= G_GRAPHS; g++) g_gstart[g] = N_NODES;
    }
    if (i < DEPTH - 1) g_bnctr[i] = 0;
}

// ---------------- degree histogram ----------------
__global__ void k_deg(const int* __restrict__ ei) {
    int e = blockIdx.x * 256 + threadIdx.x;
    if (e < N_EDGES) atomicAdd(&g_rowcnt[ei[N_EDGES + e]], 1);
}

// ---------------- scan stage 1: per-block sums -----------------------------
__global__ __launch_bounds__(256) void k_scan1() {
    __shared__ int wsum[8];
    int t = threadIdx.x, lane = t & 31, w = t >> 5;
    int i = blockIdx.x * 256 + t;
    int v = (i < N_NODES) ? g_rowcnt[i] : 0;
    int s = v;
#pragma unroll
    for (int off = 1; off < 32; off <<= 1) {
        int tmp = __shfl_up_sync(0xffffffffu, s, off);
        if (lane >= off) s += tmp;
    }
    if (lane == 31) wsum[w] = s;
    __syncthreads();
    if (t == 0) {
        int tot = 0;
#pragma unroll
        for (int j = 0; j < 8; j++) tot += wsum[j];
        g_blocksum[blockIdx.x] = tot;
    }
}

// scan stage 2 (fused): each block rescans the 196 block sums, then finishes
// rowptr/cursor/dinv for its 256 nodes.
__global__ __launch_bounds__(256) void k_scan3() {
    __shared__ int wsum[8];
    __shared__ int s_off[256];
    int t = threadIdx.x, lane = t & 31, w = t >> 5;
    {
        int v = (t < SCAN_BLOCKS) ? g_blocksum[t] : 0;
        int s = v;
#pragma unroll
        for (int off = 1; off < 32; off <<= 1) {
            int tmp = __shfl_up_sync(0xffffffffu, s, off);
            if (lane >= off) s += tmp;
        }
        if (lane == 31) wsum[w] = s;
        __syncthreads();
        if (t == 0) {
            int run = 0;
#pragma unroll
            for (int j = 0; j < 8; j++) { int x = wsum[j]; wsum[j] = run; run += x; }
        }
        __syncthreads();
        s_off[t] = wsum[w] + s - v;
        __syncthreads();
    }
    const int base = s_off[blockIdx.x];
    __syncthreads();

    int i = blockIdx.x * 256 + t;
    int v = (i < N_NODES) ? g_rowcnt[i] : 0;
    int s = v;
#pragma unroll
    for (int off = 1; off < 32; off <<= 1) {
        int tmp = __shfl_up_sync(0xffffffffu, s, off);
        if (lane >= off) s += tmp;
    }
    if (lane == 31) wsum[w] = s;
    __syncthreads();
    if (t == 0) {
        int run = 0;
#pragma unroll
        for (int j = 0; j < 8; j++) { int x = wsum[j]; wsum[j] = run; run += x; }
    }
    __syncthreads();
    if (i < N_NODES) {
        int excl = base + wsum[w] + s - v;
        g_rowptr[i] = excl;
        g_cursor[i] = excl;
        g_dinv[i]   = rsqrtf((float)v + 1.0f);
    }
    if (blockIdx.x == 0 && t == 0) g_rowptr[N_NODES] = N_EDGES;
}

// ---------------- CSR fill: packed {src, full norm} ----------------
__global__ void k_fill(const int* __restrict__ ei) {
    int e = blockIdx.x * 256 + threadIdx.x;
    if (e >= N_EDGES) return;
    int src = ei[e];
    int dst = ei[N_EDGES + e];
    int pos = atomicAdd(&g_cursor[dst], 1);
    float norm = g_dinv[src] * g_dinv[dst];
    g_csr[pos] = make_int2(src, __float_as_int(norm));
}

// ---------------- GEMM (FFMA2): C = pre(A) @ W (+bias) ---------------------
// A staged TRANSPOSED (sAT[k][m], pad 66 keeps LDS.64 8B-aligned) so M-row-
// pairs load DIRECTLY as 64-bit values (no pack movs) for fma.rn.f32x2.
// If bn != null: a <- max(a,0)*bn[k] + bn[128+k] fused on load.
__global__ __launch_bounds__(256) void k_gemm(const float* __restrict__ A,
                                              const float* __restrict__ W,
                                              const float* __restrict__ bias,
                                              const float* __restrict__ bn,
                                              float* __restrict__ C,
                                              int nrows) {
    __shared__ float sAT[32][66];
    __shared__ float sW[32][128];
    const int tid = threadIdx.x;
    const int tx  = tid & 31;    // -> cols tx*4 .. tx*4+3
    const int ty  = tid >> 5;    // -> rows ty*8 .. ty*8+7
    const int m0  = blockIdx.x * 64;

    unsigned long long acc[4][4];   // [row-pair][col]
#pragma unroll
    for (int p = 0; p < 4; p++)
#pragma unroll
        for (int c = 0; c < 4; c++) acc[p][c] = 0ull;

    for (int kc = 0; kc < 128; kc += 32) {
#pragma unroll
        for (int i = 0; i < 8; i++) {
            int idx = tid + i * 256;
            int m = idx >> 5, k = idx & 31;
            int row = m0 + m;
            float a = (row < nrows) ? A[row * 128 + kc + k] : 0.f;
            if (bn != nullptr)
                a = fmaxf(a, 0.f) * bn[kc + k] + bn[HDIM + kc + k];
            sAT[k][m] = a;
        }
#pragma unroll
        for (int i = 0; i < 16; i++) {
            int idx = tid + i * 256;
            int k = idx >> 7, n = idx & 127;
            sW[k][n] = W[(kc + k) * 128 + n];
        }
        __syncthreads();
#pragma unroll
        for (int k = 0; k < 32; k++) {
            const float* ar = &sAT[k][ty * 8];
            unsigned long long ap[4] = {
                *(const unsigned long long*)(ar + 0),
                *(const unsigned long long*)(ar + 2),
                *(const unsigned long long*)(ar + 4),
                *(const unsigned long long*)(ar + 6)
            };
            float4 w = *(const float4*)&sW[k][tx * 4];
            unsigned long long wp[4] = {
                pack2(w.x, w.x), pack2(w.y, w.y),
                pack2(w.z, w.z), pack2(w.w, w.w)
            };
#pragma unroll
            for (int p = 0; p < 4; p++)
#pragma unroll
                for (int c = 0; c < 4; c++)
                    fma2(acc[p][c], ap[p], wp[c]);
        }
        __syncthreads();
    }
#pragma unroll
    for (int r = 0; r < 8; r++) {
        int row = m0 + ty * 8 + r;
        if (row < nrows) {
            int p = r >> 1;
            float4 v;
            if (r & 1) {
                v.x = hi32(acc[p][0]); v.y = hi32(acc[p][1]);
                v.z = hi32(acc[p][2]); v.w = hi32(acc[p][3]);
            } else {
                v.x = lo32(acc[p][0]); v.y = lo32(acc[p][1]);
                v.z = lo32(acc[p][2]); v.w = lo32(acc[p][3]);
            }
            if (bias != nullptr) {
                v.x += bias[tx * 4 + 0]; v.y += bias[tx * 4 + 1];
                v.z += bias[tx * 4 + 2]; v.w += bias[tx * 4 + 3];
            }
            *(float4*)&C[row * 128 + tx * 4] = v;
        }
    }
}

// ---------------- pull aggregation: one warp per dst node (independent) ----
__global__ __launch_bounds__(256) void k_agg(const float* __restrict__ bias) {
    int node = blockIdx.x * 8 + (threadIdx.x >> 5);
    if (node >= N_NODES) return;
    int lane = threadIdx.x & 31;
    int beg = g_rowptr[node], end = g_rowptr[node + 1];
    float dv = g_dinv[node];

    float4 acc = make_float4(0.f, 0.f, 0.f, 0.f);
#pragma unroll 4
    for (int j = beg; j < end; j++) {
        int2 ed  = __ldg(&g_csr[j]);             // one LDG.64, warp-broadcast
        float nw = __int_as_float(ed.y);
        float4 v = g_hw4[ed.x * 32 + lane];
        acc.x += nw * v.x; acc.y += nw * v.y;
        acc.z += nw * v.z; acc.w += nw * v.w;
    }
    float d2 = dv * dv;
    float4 s = g_hw4[node * 32 + lane];
    acc.x = acc.x + d2 * s.x + bias[lane * 4 + 0];
    acc.y = acc.y + d2 * s.y + bias[lane * 4 + 1];
    acc.z = acc.z + d2 * s.z + bias[lane * 4 + 2];
    acc.w = acc.w + d2 * s.w + bias[lane * 4 + 3];
    g_agg4[node * 32 + lane] = acc;
}

// ---------------- BN: partials + fused last-block finalize -----------------
__global__ __launch_bounds__(128) void k_bnreduce(const float* __restrict__ gamma,
                                                  const float* __restrict__ beta,
                                                  int layer) {
    const int c = threadIdx.x;
    const int rows_per = 200;                 // 250 * 200 = 50000
    int r0 = blockIdx.x * rows_per;
    int r1 = r0 + rows_per; if (r1 > N_NODES) r1 = N_NODES;
    const float* agg = (const float*)g_agg4;
    float s = 0.f, q = 0.f;
    for (int r = r0; r < r1; r++) {
        float v = fmaxf(__ldg(&agg[r * HDIM + c]), 0.f);
        s += v; q += v * v;
    }
    g_part[blockIdx.x * 2 * HDIM + c] = s;
    g_part[blockIdx.x * 2 * HDIM + HDIM + c] = q;

    __threadfence();
    __shared__ int s_last;
    if (c == 0) s_last = (atomicAdd(&g_bnctr[layer], 1) == 249) ? 1 : 0;
    __syncthreads();
    if (s_last) {
        float ts = 0.f, tq = 0.f;
        for (int b = 0; b < 250; b++) {
            ts += g_part[b * 2 * HDIM + c];
            tq += g_part[b * 2 * HDIM + HDIM + c];
        }
        float inv_n = 1.0f / (float)N_NODES;
        float mu  = ts * inv_n;
        float var = tq * inv_n - mu * mu;
        float sc  = rsqrtf(var + BN_EPS) * gamma[c];
        g_bn[c]        = sc;
        g_bn[HDIM + c] = beta[c] - mu * sc;
    }
}

// ---------------- pooling: one block per graph (batch sorted, no atomics) --
__global__ __launch_bounds__(128) void k_pool(float* __restrict__ out) {
    int g = blockIdx.x, c = threadIdx.x;
    int r0 = g_gstart[g], r1 = g_gstart[g + 1];
    const float* agg = (const float*)g_agg4;
    float s = 0.f;
    for (int r = r0; r < r1; r++) s += __ldg(&agg[r * HDIM + c]);
    out[g * HDIM + c] = s / fmaxf((float)(r1 - r0), 1.0f);
}

// ---------------- launcher: fork-join overlap of prep and early GEMMs ------
extern "C" void kernel_launch(void* const* d_in, const int* in_sizes, int n_in,
                              void* d_out, int out_size) {
    const float* x      = (const float*)d_in[0];
    const int*   ei     = (const int*)d_in[1];     // int32 (JAX coerces int64)
    const int*   batch  = (const int*)d_in[2];     // int32
    const float* W_emb  = (const float*)d_in[3];
    const float* b_emb  = (const float*)d_in[4];
    const float* W_conv = (const float*)d_in[5];
    const float* b_conv = (const float*)d_in[6];
    const float* gamma  = (const float*)d_in[7];
    const float* beta   = (const float*)d_in[8];
    float* out = (float*)d_out;

    float *p_h, *p_hw, *p_agg, *p_bn;
    cudaGetSymbolAddress((void**)&p_h,   g_h4);
    cudaGetSymbolAddress((void**)&p_hw,  g_hw4);
    cudaGetSymbolAddress((void**)&p_agg, g_agg4);
    cudaGetSymbolAddress((void**)&p_bn,  g_bn);

    const int GEMM_BLOCKS = (N_NODES + 63) / 64;          // 782
    const int NODE_BLOCKS = (N_NODES + 255) / 256;        // 196
    const int EDGE_BLOCKS = (N_EDGES + 255) / 256;        // 3125
    const int AGG_BLOCKS  = N_NODES / 8;                  // 6250 (exact)

    // Side stream + fork/join events (not destroyed: destroying a stream
    // mid-capture invalidates the capture; kernel_launch runs only a few
    // times so the leak is bounded and tiny).
    cudaStream_t s2;
    cudaStreamCreateWithFlags(&s2, cudaStreamNonBlocking);
    cudaEvent_t evF, evJ;
    cudaEventCreateWithFlags(&evF, cudaEventDisableTiming);
    cudaEventCreateWithFlags(&evJ, cudaEventDisableTiming);

    // fork: s2 joins the capture graph
    cudaEventRecord(evF, 0);
    cudaStreamWaitEvent(s2, evF, 0);

    // stream 0: CSR preprocessing chain (depends only on edge_index/batch)
    k_init<<<NODE_BLOCKS, 256>>>(batch);
    k_deg<<<EDGE_BLOCKS, 256>>>(ei);
    k_scan1<<<SCAN_BLOCKS, 256>>>();
    k_scan3<<<SCAN_BLOCKS, 256>>>();
    k_fill<<<EDGE_BLOCKS, 256>>>(ei);

    // stream s2: embedding GEMM + conv-0 GEMM (depend only on x/W)
    k_gemm<<<GEMM_BLOCKS, 256, 0, s2>>>(x, W_emb, b_emb, nullptr, p_h, N_NODES);
    k_gemm<<<GEMM_BLOCKS, 256, 0, s2>>>(p_h, W_conv, nullptr, nullptr,
                                        p_hw, N_NODES);

    // join: k_agg(0) needs both the CSR (stream 0) and hw (s2)
    cudaEventRecord(evJ, s2);
    cudaStreamWaitEvent(0, evJ, 0);

    for (int i = 0; i < DEPTH; i++) {
        if (i > 0) {
            // fused relu+BN of prev layer applied on GEMM load
            k_gemm<<<GEMM_BLOCKS, 256>>>(p_agg, W_conv + i * HDIM * HDIM,
                                         nullptr, p_bn, p_hw, N_NODES);
        }
        k_agg<<<AGG_BLOCKS, 256>>>(b_conv + i * HDIM);
        if (i < DEPTH - 1)
            k_bnreduce<<<250, 128>>>(gamma + i * HDIM, beta + i * HDIM, i);
    }

    k_pool<<<G_GRAPHS, 128>>>(out);
}